// round 2
// baseline (speedup 1.0000x reference)
#include <cuda_runtime.h>
#include <math.h>

// Problem dims
#define Bb 16
#define Ss 64
#define Rr 6
#define Ll 24
#define Dd 128
#define Hh 256
#define BS 1024      // B*S
#define NSEQ 6144    // B*S*R

// ---------------- scratch (device globals; no allocations allowed) ----------------
__device__ float g_Wbig[4 * 256 * 384];    // [group][unit][k] gate weights, zero padded
__device__ float g_hA[NSEQ * Hh];
__device__ float g_hB[NSEQ * Hh];
__device__ float g_his_last[NSEQ * Hh];
__device__ float g_intra_h[BS * Hh];       // (16,64,256) == flat_h rows (b*64+t)
__device__ float g_Mrv[NSEQ * 384];
__device__ float g_mpv[BS * 384];
__device__ float g_hp[BS * 257];
__device__ float g_qi[BS * Hh];
__device__ float g_ki[NSEQ * Hh];
__device__ float g_vi[NSEQ * Hh];
__device__ float g_oi[BS * Hh];
__device__ float g_vv[BS * Hh];
__device__ float g_qh[BS * Hh];
__device__ float g_kh[BS * Hh];
__device__ float g_vhp[BS * Hh];
__device__ float g_oh[BS * Hh];
__device__ float g_vh[BS * Hh];
__device__ float g_feat[BS * 640];

__device__ __forceinline__ float sigmoidf_(float x) { return 1.f / (1.f + expf(-x)); }

// ---------------- build combined gate weight matrix ----------------
// Layout: g_Wbig[(g*256 + j)*384 + k]
//   g=0 : r gate  : k<128 -> w_ih[j],      k>=128 -> w_hh[j]
//   g=1 : z gate  : k<128 -> w_ih[256+j],  k>=128 -> w_hh[256+j]
//   g=2 : xn      : k<128 -> w_ih[512+j],  else 0
//   g=3 : hn      : k<128 -> 0, else w_hh[512+j]
__global__ void prep_wbig(const float* __restrict__ w_ih, const float* __restrict__ w_hh) {
    int idx = blockIdx.x * blockDim.x + threadIdx.x;
    if (idx >= 4 * 256 * 384) return;
    int k = idx % 384;
    int row = idx / 384;
    int g = row >> 8;
    int j = row & 255;
    float v = 0.f;
    if (g == 0) v = (k < 128) ? w_ih[j * 128 + k] : w_hh[j * 256 + (k - 128)];
    else if (g == 1) v = (k < 128) ? w_ih[(256 + j) * 128 + k] : w_hh[(256 + j) * 256 + (k - 128)];
    else if (g == 2) v = (k < 128) ? w_ih[(512 + j) * 128 + k] : 0.f;
    else v = (k < 128) ? 0.f : w_hh[(512 + j) * 256 + (k - 128)];
    g_Wbig[idx] = v;
}

// ---------------- fused GRU step ----------------
// Block: 64 rows x 64 hidden units (x4 gate slots). Threads 256 (ty=tid>>5, tx=tid&31).
// Thread owns rows ty*8..+7 and units {tx, tx+32}; acc[r][m] with m = 2*group + up.
__global__ void __launch_bounds__(256) gru_step(
    int nrows,
    const float* __restrict__ x, int x_stride,   // x already offset to step t
    int mode,                                    // 0 = inter (g_hA/g_hB), 1 = intra (g_intra_h)
    int t,
    const float* __restrict__ b_ih, const float* __restrict__ b_hh,
    const int* __restrict__ lenp)
{
    const float* h_in;
    float* h_out;
    int h_stride;
    bool first = (t == 0);
    if (mode == 0) {
        h_in  = (t & 1) ? g_hB : g_hA;
        h_out = (t & 1) ? g_hA : g_hB;
        h_stride = 256;
    } else {
        h_in  = first ? g_intra_h : (g_intra_h + (t - 1) * 256);
        h_out = g_intra_h + t * 256;
        h_stride = Ss * 256;
    }

    int i0 = blockIdx.x * 64;
    int j0 = blockIdx.y * 64;
    int tid = threadIdx.x;
    int ty = tid >> 5, tx = tid & 31;

    __shared__ float As[64][17];
    __shared__ float Bs[192][17];

    float acc[8][8];
#pragma unroll
    for (int r = 0; r < 8; r++)
#pragma unroll
        for (int m = 0; m < 8; m++) acc[r][m] = 0.f;

    // ---- Phase X: k = 0..127 over x; groups {r, z, xn} -> acc m 0..5
    for (int k0 = 0; k0 < 128; k0 += 16) {
        for (int l = tid; l < 64 * 16; l += 256) {
            int r = l >> 4, kk = l & 15;
            int gi = i0 + r;
            As[r][kk] = (gi < nrows) ? x[(long)gi * x_stride + k0 + kk] : 0.f;
        }
        for (int l = tid; l < 192 * 16; l += 256) {
            int c = l >> 4, kk = l & 15;
            int g = c >> 6;           // 0,1,2
            int u = c & 63;
            Bs[c][kk] = g_Wbig[((g << 8) + j0 + u) * 384 + k0 + kk];
        }
        __syncthreads();
#pragma unroll
        for (int kk = 0; kk < 16; kk++) {
            float a[8], b[6];
#pragma unroll
            for (int r = 0; r < 8; r++) a[r] = As[ty * 8 + r][kk];
#pragma unroll
            for (int m = 0; m < 6; m++) b[m] = Bs[m * 32 + tx][kk];
#pragma unroll
            for (int r = 0; r < 8; r++)
#pragma unroll
                for (int m = 0; m < 6; m++) acc[r][m] += a[r] * b[m];
        }
        __syncthreads();
    }

    // ---- Phase H: k = 0..255 over h; groups {r, z, hn} -> acc m {0,1,2,3,6,7}
    if (!first) {
        for (int k0 = 0; k0 < 256; k0 += 16) {
            for (int l = tid; l < 64 * 16; l += 256) {
                int r = l >> 4, kk = l & 15;
                int gi = i0 + r;
                As[r][kk] = (gi < nrows) ? h_in[(long)gi * h_stride + k0 + kk] : 0.f;
            }
            for (int l = tid; l < 192 * 16; l += 256) {
                int c = l >> 4, kk = l & 15;
                int g = (c < 128) ? (c >> 6) : 3;   // 0,1,3
                int u = c & 63;
                Bs[c][kk] = g_Wbig[((g << 8) + j0 + u) * 384 + 128 + k0 + kk];
            }
            __syncthreads();
#pragma unroll
            for (int kk = 0; kk < 16; kk++) {
                float a[8], b[6];
#pragma unroll
                for (int r = 0; r < 8; r++) a[r] = As[ty * 8 + r][kk];
#pragma unroll
                for (int mp = 0; mp < 6; mp++) b[mp] = Bs[mp * 32 + tx][kk];
#pragma unroll
                for (int r = 0; r < 8; r++) {
#pragma unroll
                    for (int mp = 0; mp < 6; mp++) {
                        int m = (mp < 4) ? mp : (mp + 2);   // 0,1,2,3,6,7
                        acc[r][m] += a[r] * b[mp];
                    }
                }
            }
            __syncthreads();
        }
    }

    // ---- gating epilogue
#pragma unroll
    for (int r = 0; r < 8; r++) {
        int gi = i0 + ty * 8 + r;
        if (gi >= nrows) continue;
        bool gather = (lenp != nullptr) && (lenp[gi] == t + 1);
#pragma unroll
        for (int up = 0; up < 2; up++) {
            int u = up * 32 + tx;
            int j = j0 + u;
            float rg = sigmoidf_(acc[r][0 + up] + b_ih[j] + b_hh[j]);
            float zg = sigmoidf_(acc[r][2 + up] + b_ih[256 + j] + b_hh[256 + j]);
            float ng = tanhf(acc[r][4 + up] + b_ih[512 + j] + rg * (acc[r][6 + up] + b_hh[512 + j]));
            float hp = first ? 0.f : h_in[(long)gi * h_stride + j];
            float hnew = (1.f - zg) * ng + zg * hp;
            h_out[(long)gi * h_stride + j] = hnew;
            if (gather) g_his_last[gi * 256 + j] = hnew;
        }
    }
}

// ---------------- generic tiled SGEMM: C[M,N] = A[M,K] @ W[N,K]^T + bias ----------------
__device__ __forceinline__ float* sel_buf(int id) {
    switch (id) {
        case 0: return g_mpv;  case 1: return g_Mrv;  case 2: return g_hp;
        case 3: return g_qi;   case 4: return g_ki;   case 5: return g_vi;
        case 6: return g_oi;   case 7: return g_vv;   case 8: return g_qh;
        case 9: return g_kh;   case 10: return g_vhp; case 11: return g_oh;
        case 12: return g_vh;  case 13: return g_feat;
    }
    return nullptr;
}

__global__ void __launch_bounds__(256) sgemm_bias(
    int M, int N, int K,
    int a_id, const float* A_ext, int lda,
    const float* __restrict__ W, int ldw,
    const float* __restrict__ bias,
    int c_id, float* C_ext, int ldc)
{
    const float* A = (a_id >= 0) ? sel_buf(a_id) : A_ext;
    float* C = (c_id >= 0) ? sel_buf(c_id) : C_ext;

    __shared__ float As[64][17];
    __shared__ float Ws[64][17];

    int i0 = blockIdx.x * 64, n0 = blockIdx.y * 64;
    int tid = threadIdx.x;
    int ty = tid >> 4, tx = tid & 15;

    float acc[4][4];
#pragma unroll
    for (int r = 0; r < 4; r++)
#pragma unroll
        for (int c = 0; c < 4; c++) acc[r][c] = 0.f;

    for (int k0 = 0; k0 < K; k0 += 16) {
        for (int l = tid; l < 64 * 16; l += 256) {
            int r = l >> 4, kk = l & 15;
            int gi = i0 + r, kg = k0 + kk;
            As[r][kk] = (gi < M && kg < K) ? A[(long)gi * lda + kg] : 0.f;
        }
        for (int l = tid; l < 64 * 16; l += 256) {
            int n = l >> 4, kk = l & 15;
            int gn = n0 + n, kg = k0 + kk;
            Ws[n][kk] = (gn < N && kg < K) ? W[(long)gn * ldw + kg] : 0.f;
        }
        __syncthreads();
#pragma unroll
        for (int kk = 0; kk < 16; kk++) {
            float a[4], b[4];
#pragma unroll
            for (int r = 0; r < 4; r++) a[r] = As[ty * 4 + r][kk];
#pragma unroll
            for (int c = 0; c < 4; c++) b[c] = Ws[tx * 4 + c][kk];
#pragma unroll
            for (int r = 0; r < 4; r++)
#pragma unroll
                for (int c = 0; c < 4; c++) acc[r][c] += a[r] * b[c];
        }
        __syncthreads();
    }

#pragma unroll
    for (int r = 0; r < 4; r++) {
        int gi = i0 + ty * 4 + r;
        if (gi >= M) continue;
#pragma unroll
        for (int c = 0; c < 4; c++) {
            int gn = n0 + tx * 4 + c;
            if (gn < N) C[(long)gi * ldc + gn] = acc[r][c] + bias[gn];
        }
    }
}

// ---------------- builders ----------------
__global__ void build_mrv(const float* __restrict__ inter_r) {
    int idx = blockIdx.x * blockDim.x + threadIdx.x;
    if (idx >= NSEQ * 384) return;
    int i = idx / 384, c = idx % 384;
    g_Mrv[idx] = (c < 256) ? g_his_last[i * 256 + c] : inter_r[i * 128 + (c - 256)];
}

__global__ void build_mpv(const float* __restrict__ intra_x) {
    int idx = blockIdx.x * blockDim.x + threadIdx.x;
    if (idx >= BS * 384) return;
    int i = idx / 384, c = idx % 384;
    float v;
    if (c < 256) v = g_intra_h[i * 256 + c];
    else if (c < 383) v = intra_x[i * 128 + (c - 256)];
    else v = 0.f;
    g_mpv[idx] = v;
}

__global__ void build_hp(const float* __restrict__ intra_x) {
    int idx = blockIdx.x * blockDim.x + threadIdx.x;
    if (idx >= BS * 257) return;
    int i = idx / 257, c = idx % 257;
    g_hp[idx] = (c < 256) ? g_intra_h[i * 256 + c] : intra_x[i * 128 + 127];
}

__global__ void build_feat(const float* __restrict__ intra_x, const float* __restrict__ wr) {
    int idx = blockIdx.x * blockDim.x + threadIdx.x;
    if (idx >= BS * 640) return;
    float e0 = expf(wr[0]), e1 = expf(wr[1]);
    float w0 = e0 / (e0 + e1), w1 = 1.f - w0;
    int i = idx / 640, c = idx % 640;
    float v;
    if (c < 256) v = w0 * g_vv[i * 256 + c] + w1 * g_vh[i * 256 + c];
    else if (c < 512) v = g_intra_h[i * 256 + (c - 256)];
    else if (c < 639) v = intra_x[i * 128 + (c - 512)];
    else v = 0.f;
    g_feat[idx] = v;
}

// ---------------- attention cores ----------------
__global__ void inter_attn() {
    int i = blockIdx.x;            // 0..1023
    int tid = threadIdx.x;         // 128
    __shared__ float p[12];
    if (tid < 12) {
        int h = tid / 6, rr = tid % 6;
        const float* qp = g_qi + i * 256 + h * 128;
        const float* kp = g_ki + (i * 6 + rr) * 256 + h * 128;
        float acc = 0.f;
        for (int d = 0; d < 128; d++) acc += qp[d] * kp[d];
        p[tid] = acc * 0.08838834764831843f;
    }
    __syncthreads();
    if (tid < 2) {
        float mx = -1e30f;
        for (int r = 0; r < 6; r++) mx = fmaxf(mx, p[tid * 6 + r]);
        float sum = 0.f;
        for (int r = 0; r < 6; r++) { float e = expf(p[tid * 6 + r] - mx); p[tid * 6 + r] = e; sum += e; }
        float inv = 1.f / sum;
        for (int r = 0; r < 6; r++) p[tid * 6 + r] *= inv;
    }
    __syncthreads();
    for (int dd = tid; dd < 256; dd += 128) {
        int h = dd >> 7;
        float acc = 0.f;
        for (int r = 0; r < 6; r++) acc += p[h * 6 + r] * g_vi[(i * 6 + r) * 256 + dd];
        g_oi[i * 256 + dd] = acc;
    }
}

__global__ void intra_attn() {
    int tq = blockIdx.x, head = blockIdx.y, b = blockIdx.z;
    int tid = threadIdx.x;   // 128
    __shared__ float p[64];
    __shared__ float invsum;
    const float* qp = g_qh + (b * 64 + tq) * 256 + head * 128;
    if (tid < 64) {
        float s = 0.f;
        if (tid <= tq) {
            const float* kp = g_kh + (b * 64 + tid) * 256 + head * 128;
            float acc = 0.f;
            for (int d = 0; d < 128; d++) acc += qp[d] * kp[d];
            s = acc * 0.08838834764831843f;
        }
        p[tid] = s;
    }
    __syncthreads();
    if (tid == 0) {
        float mx = -1e30f;
        for (int k = 0; k <= tq; k++) mx = fmaxf(mx, p[k]);
        float sum = 0.f;
        for (int k = 0; k <= tq; k++) { float e = expf(p[k] - mx); p[k] = e; sum += e; }
        invsum = 1.f / sum;
    }
    __syncthreads();
    float inv = invsum;
    {
        int d = tid;   // 0..127
        float acc = 0.f;
        for (int k = 0; k <= tq; k++) acc += p[k] * g_vhp[(b * 64 + k) * 256 + head * 128 + d];
        g_oh[(b * 64 + tq) * 256 + head * 128 + d] = acc * inv;
    }
}

// ---------------- launch ----------------
extern "C" void kernel_launch(void* const* d_in, const int* in_sizes, int n_in,
                              void* d_out, int out_size) {
    const float* intra_x   = (const float*)d_in[0];
    const float* inter_his = (const float*)d_in[1];
    const float* inter_r   = (const float*)d_in[2];
    /* d_in[3] intra_mask: unused by reference */
    const int*   inter_len = (const int*)d_in[4];
    const float* w_ih = (const float*)d_in[5];
    const float* w_hh = (const float*)d_in[6];
    const float* b_ih = (const float*)d_in[7];
    const float* b_hh = (const float*)d_in[8];
    const float* iq_w = (const float*)d_in[9];
    const float* iq_b = (const float*)d_in[10];
    const float* ik_w = (const float*)d_in[11];
    const float* ik_b = (const float*)d_in[12];
    const float* iv_w = (const float*)d_in[13];
    const float* iv_b = (const float*)d_in[14];
    const float* io_w = (const float*)d_in[15];
    const float* io_b = (const float*)d_in[16];
    const float* aq_w = (const float*)d_in[17];
    const float* aq_b = (const float*)d_in[18];
    const float* ak_w = (const float*)d_in[19];
    const float* ak_b = (const float*)d_in[20];
    const float* av_w = (const float*)d_in[21];
    const float* av_b = (const float*)d_in[22];
    const float* ao_w = (const float*)d_in[23];
    const float* ao_b = (const float*)d_in[24];
    const float* wr   = (const float*)d_in[25];
    const float* ln_w = (const float*)d_in[26];
    const float* ln_b = (const float*)d_in[27];
    float* out = (float*)d_out;

    // gate weight pack
    prep_wbig<<<(4 * 256 * 384 + 255) / 256, 256>>>(w_ih, w_hh);

    // inter GRU: 6144 sequences x 24 steps; scatter his_last at len-1
    for (int t = 0; t < Ll; t++) {
        gru_step<<<dim3(96, 4), 256>>>(NSEQ, inter_his + t * Dd, Ll * Dd, 0, t,
                                       b_ih, b_hh, inter_len);
    }
    // intra GRU: 16 sequences x 64 steps; states stored into g_intra_h (16,64,256)
    for (int t = 0; t < Ss; t++) {
        gru_step<<<dim3(1, 4), 256>>>(Bb, intra_x + t * Dd, Ss * Dd, 1, t,
                                      b_ih, b_hh, nullptr);
    }

    // builders
    build_mrv<<<(NSEQ * 384 + 255) / 256, 256>>>(inter_r);
    build_mpv<<<(BS * 384 + 255) / 256, 256>>>(intra_x);
    build_hp<<<(BS * 257 + 255) / 256, 256>>>(intra_x);

    // inter MHA projections
    sgemm_bias<<<dim3(16, 4), 256>>>(1024, 256, 383, 0, nullptr, 384, iq_w, 383, iq_b, 3, nullptr, 256);
    sgemm_bias<<<dim3(96, 4), 256>>>(6144, 256, 383, 1, nullptr, 384, ik_w, 383, ik_b, 4, nullptr, 256);
    sgemm_bias<<<dim3(96, 4), 256>>>(6144, 256, 384, 1, nullptr, 384, iv_w, 384, iv_b, 5, nullptr, 256);
    inter_attn<<<1024, 128>>>();
    sgemm_bias<<<dim3(16, 4), 256>>>(1024, 256, 256, 6, nullptr, 256, io_w, 256, io_b, 7, nullptr, 256);

    // intra MHA projections (q,k use intra_x[:, :127] directly via lda=128)
    sgemm_bias<<<dim3(16, 4), 256>>>(1024, 256, 127, -1, intra_x, 128, aq_w, 127, aq_b, 8, nullptr, 256);
    sgemm_bias<<<dim3(16, 4), 256>>>(1024, 256, 127, -1, intra_x, 128, ak_w, 127, ak_b, 9, nullptr, 256);
    sgemm_bias<<<dim3(16, 4), 256>>>(1024, 256, 257, 2, nullptr, 257, av_w, 257, av_b, 10, nullptr, 256);
    intra_attn<<<dim3(64, 2, 16), 128>>>();
    sgemm_bias<<<dim3(16, 4), 256>>>(1024, 256, 256, 11, nullptr, 256, ao_w, 256, ao_b, 12, nullptr, 256);

    // combine + final projection
    build_feat<<<(BS * 640 + 255) / 256, 256>>>(intra_x, wr);
    sgemm_bias<<<dim3(16, 4), 256>>>(1024, 256, 639, 13, nullptr, 640, ln_w, 639, ln_b, -1, out, 256);
}

// round 3
// speedup vs baseline: 2.4532x; 2.4532x over previous
#include <cuda_runtime.h>
#include <mma.h>
#include <math.h>
using namespace nvcuda;

// Problem dims
#define Bb 16
#define Ss 64
#define Rr 6
#define Ll 24
#define Dd 128
#define Hh 256
#define BS 1024      // B*S
#define NSEQ 6144    // B*S*R
#define NROWS_XW (NSEQ * Ll)   // 147456

// ---------------- scratch (device globals; no allocations allowed) ----------------
__device__ float g_xw_inter[(size_t)NROWS_XW * 768];  // 452 MB
__device__ float g_xw_intra[BS * 768];
__device__ float g_gh[NSEQ * 768];
__device__ float g_hA[NSEQ * Hh];
__device__ float g_hB[NSEQ * Hh];
__device__ float g_his_last[NSEQ * Hh];
__device__ float g_intra_h[BS * Hh];
__device__ float g_Mrv[NSEQ * 384];
__device__ float g_mpv[BS * 384];
__device__ float g_hp[BS * 288];          // 257 used, padded to 288 (zeros)
__device__ float g_qi[BS * Hh];
__device__ float g_ki[NSEQ * Hh];
__device__ float g_vi[NSEQ * Hh];
__device__ float g_oi[BS * Hh];
__device__ float g_vv[BS * Hh];
__device__ float g_qh[BS * Hh];
__device__ float g_kh[BS * Hh];
__device__ float g_vhp[BS * Hh];
__device__ float g_oh[BS * Hh];
__device__ float g_vh[BS * Hh];
__device__ float g_feat[BS * 640];
// padded weights (K rounded up to multiple of 32, tail zeros)
__device__ float g_Wq[256 * 384];
__device__ float g_Wk[256 * 384];
__device__ float g_Waq[256 * 128];
__device__ float g_Wak[256 * 128];
__device__ float g_Wav[256 * 288];
__device__ float g_Wln[256 * 640];

__device__ __forceinline__ float sigmoidf_(float x) { return 1.f / (1.f + expf(-x)); }

// ---------------- weight padding ----------------
__global__ void pad_w(const float* __restrict__ src, float* __restrict__ dst,
                      int N, int Ks, int Kd) {
    int idx = blockIdx.x * blockDim.x + threadIdx.x;
    if (idx >= N * Kd) return;
    int n = idx / Kd, k = idx % Kd;
    dst[idx] = (k < Ks) ? src[n * Ks + k] : 0.f;
}

// ---------------- tf32 tensor-core GEMM: C[M,N] = A[M,K] @ W[N,K]^T (+bias) --------
// Block 256 threads (8 warps as 4x2), tile 128x64, k-chunk 32, wmma m16n16k8 tf32.
__global__ void __launch_bounds__(256) gemm_tc(
    int M, int N, int K,
    const float* __restrict__ A, int lda,
    const float* __restrict__ W, int ldw,
    const float* __restrict__ bias,
    float* __restrict__ C, int ldc)
{
    __shared__ float smem[128 * 68];          // max(As+Bs, Cs)
    float* As = smem;                         // [128][40]
    float* Bs = smem + 128 * 40;              // [64][40]

    int i0 = blockIdx.x * 128, n0 = blockIdx.y * 64;
    int tid = threadIdx.x;
    int warp = tid >> 5;
    int wy = warp >> 1, wx = warp & 1;

    wmma::fragment<wmma::accumulator, 16, 16, 8, float> acc[2][2];
#pragma unroll
    for (int a = 0; a < 2; a++)
#pragma unroll
        for (int b = 0; b < 2; b++) wmma::fill_fragment(acc[a][b], 0.f);

    for (int k0 = 0; k0 < K; k0 += 32) {
#pragma unroll
        for (int it = 0; it < 4; it++) {
            int idx = tid + it * 256;
            int r = idx >> 3, k4 = (idx & 7) << 2;
            float4 v = make_float4(0.f, 0.f, 0.f, 0.f);
            int gi = i0 + r;
            if (gi < M) v = *(const float4*)(A + (size_t)gi * lda + k0 + k4);
            *(float4*)(As + r * 40 + k4) = v;
        }
#pragma unroll
        for (int it = 0; it < 2; it++) {
            int idx = tid + it * 256;
            int n = idx >> 3, k4 = (idx & 7) << 2;
            float4 v = *(const float4*)(W + (size_t)(n0 + n) * ldw + k0 + k4);
            *(float4*)(Bs + n * 40 + k4) = v;
        }
        __syncthreads();
#pragma unroll
        for (int kk = 0; kk < 32; kk += 8) {
            wmma::fragment<wmma::matrix_a, 16, 16, 8, wmma::precision::tf32, wmma::row_major> af[2];
            wmma::fragment<wmma::matrix_b, 16, 16, 8, wmma::precision::tf32, wmma::col_major> bf[2];
#pragma unroll
            for (int fy = 0; fy < 2; fy++) {
                wmma::load_matrix_sync(af[fy], As + (wy * 32 + fy * 16) * 40 + kk, 40);
#pragma unroll
                for (int e = 0; e < af[fy].num_elements; e++)
                    af[fy].x[e] = wmma::__float_to_tf32(af[fy].x[e]);
            }
#pragma unroll
            for (int fx = 0; fx < 2; fx++) {
                wmma::load_matrix_sync(bf[fx], Bs + (wx * 32 + fx * 16) * 40 + kk, 40);
#pragma unroll
                for (int e = 0; e < bf[fx].num_elements; e++)
                    bf[fx].x[e] = wmma::__float_to_tf32(bf[fx].x[e]);
            }
#pragma unroll
            for (int fy = 0; fy < 2; fy++)
#pragma unroll
                for (int fx = 0; fx < 2; fx++)
                    wmma::mma_sync(acc[fy][fx], af[fy], bf[fx], acc[fy][fx]);
        }
        __syncthreads();
    }

    float* Cs = smem;  // [128][68]
#pragma unroll
    for (int fy = 0; fy < 2; fy++)
#pragma unroll
        for (int fx = 0; fx < 2; fx++)
            wmma::store_matrix_sync(Cs + (wy * 32 + fy * 16) * 68 + wx * 32 + fx * 16,
                                    acc[fy][fx], 68, wmma::mem_row_major);
    __syncthreads();
#pragma unroll
    for (int it = 0; it < 8; it++) {
        int idx = tid + it * 256;
        int r = idx >> 4, c4 = (idx & 15) << 2;
        int gi = i0 + r;
        if (gi >= M) continue;
        float4 v = *(float4*)(Cs + r * 68 + c4);
        if (bias) {
            v.x += bias[n0 + c4];     v.y += bias[n0 + c4 + 1];
            v.z += bias[n0 + c4 + 2]; v.w += bias[n0 + c4 + 3];
        }
        *(float4*)(C + (size_t)gi * ldc + n0 + c4) = v;
    }
}

// ---------------- inter-GRU gating (elementwise, bandwidth kernel) ----------------
__device__ __forceinline__ float gate1(float xr, float xz, float xn,
                                       float gr, float gz, float gn, float hp,
                                       float bir, float biz, float bin,
                                       float bhr, float bhz, float bhn) {
    float r = sigmoidf_(xr + bir + gr + bhr);
    float z = sigmoidf_(xz + biz + gz + bhz);
    float n = tanhf(xn + bin + r * (gn + bhn));
    return (1.f - z) * n + z * hp;
}

__global__ void gru_gate(int t, int has_gh,
    const float* __restrict__ xw, const float* __restrict__ gh,
    const float* __restrict__ h_prev, float* __restrict__ h_out,
    const float* __restrict__ b_ih, const float* __restrict__ b_hh,
    const int* __restrict__ lenp, float* __restrict__ his_last)
{
    int idx = blockIdx.x * blockDim.x + threadIdx.x;
    if (idx >= NSEQ * 64) return;
    int i = idx >> 6;
    int q = (idx & 63) << 2;
    const float* xwrow = xw + ((size_t)i * Ll + t) * 768;
    float4 xr = *(const float4*)(xwrow + q);
    float4 xz = *(const float4*)(xwrow + 256 + q);
    float4 xn = *(const float4*)(xwrow + 512 + q);
    float4 gr = make_float4(0.f, 0.f, 0.f, 0.f), gz = gr, gn = gr, hp = gr;
    if (has_gh) {
        const float* ghrow = gh + (size_t)i * 768;
        gr = *(const float4*)(ghrow + q);
        gz = *(const float4*)(ghrow + 256 + q);
        gn = *(const float4*)(ghrow + 512 + q);
        hp = *(const float4*)(h_prev + (size_t)i * 256 + q);
    }
    float4 bir = *(const float4*)(b_ih + q);
    float4 biz = *(const float4*)(b_ih + 256 + q);
    float4 bin = *(const float4*)(b_ih + 512 + q);
    float4 bhr = *(const float4*)(b_hh + q);
    float4 bhz = *(const float4*)(b_hh + 256 + q);
    float4 bhn = *(const float4*)(b_hh + 512 + q);
    float4 h;
    h.x = gate1(xr.x, xz.x, xn.x, gr.x, gz.x, gn.x, hp.x, bir.x, biz.x, bin.x, bhr.x, bhz.x, bhn.x);
    h.y = gate1(xr.y, xz.y, xn.y, gr.y, gz.y, gn.y, hp.y, bir.y, biz.y, bin.y, bhr.y, bhz.y, bhn.y);
    h.z = gate1(xr.z, xz.z, xn.z, gr.z, gz.z, gn.z, hp.z, bir.z, biz.z, bin.z, bhr.z, bhz.z, bhn.z);
    h.w = gate1(xr.w, xz.w, xn.w, gr.w, gz.w, gn.w, hp.w, bir.w, biz.w, bin.w, bhr.w, bhz.w, bhn.w);
    *(float4*)(h_out + (size_t)i * 256 + q) = h;
    if (lenp[i] == t + 1) *(float4*)(his_last + (size_t)i * 256 + q) = h;
}

// ---------------- fused intra GRU: one block per batch element, 64 steps ----------
__global__ void __launch_bounds__(768) intra_gru(
    const float* __restrict__ xw_intra,
    const float* __restrict__ w_hh,
    const float* __restrict__ b_ih, const float* __restrict__ b_hh,
    float* __restrict__ intra_h)
{
    int b = blockIdx.x;
    int tid = threadIdx.x;   // 0..767
    __shared__ float h_sh[256];
    __shared__ float gh_sh[768];
    if (tid < 256) h_sh[tid] = 0.f;
    __syncthreads();
    const float4* w4 = (const float4*)(w_hh + (size_t)tid * 256);
    for (int t = 0; t < Ss; t++) {
        float acc = 0.f;
        const float4* h4 = (const float4*)h_sh;
#pragma unroll 16
        for (int k = 0; k < 64; k++) {
            float4 w = w4[k];
            float4 h = h4[k];
            acc += w.x * h.x + w.y * h.y + w.z * h.z + w.w * h.w;
        }
        gh_sh[tid] = acc;
        __syncthreads();
        if (tid < 256) {
            const float* xwrow = xw_intra + ((size_t)b * Ss + t) * 768;
            float r = sigmoidf_(xwrow[tid] + b_ih[tid] + gh_sh[tid] + b_hh[tid]);
            float z = sigmoidf_(xwrow[256 + tid] + b_ih[256 + tid] + gh_sh[256 + tid] + b_hh[256 + tid]);
            float n = tanhf(xwrow[512 + tid] + b_ih[512 + tid] + r * (gh_sh[512 + tid] + b_hh[512 + tid]));
            float hn = (1.f - z) * n + z * h_sh[tid];
            h_sh[tid] = hn;
            intra_h[((size_t)b * Ss + t) * 256 + tid] = hn;
        }
        __syncthreads();
    }
}

// ---------------- builders ----------------
__global__ void build_mrv(const float* __restrict__ inter_r,
                          const float* __restrict__ his_last, float* __restrict__ Mrv) {
    int idx = blockIdx.x * blockDim.x + threadIdx.x;
    if (idx >= NSEQ * 384) return;
    int i = idx / 384, c = idx % 384;
    Mrv[idx] = (c < 256) ? his_last[i * 256 + c] : inter_r[i * 128 + (c - 256)];
}

__global__ void build_mpv(const float* __restrict__ intra_x,
                          const float* __restrict__ intra_h, float* __restrict__ mpv) {
    int idx = blockIdx.x * blockDim.x + threadIdx.x;
    if (idx >= BS * 384) return;
    int i = idx / 384, c = idx % 384;
    float v;
    if (c < 256) v = intra_h[i * 256 + c];
    else if (c < 383) v = intra_x[i * 128 + (c - 256)];
    else v = 0.f;
    mpv[idx] = v;
}

__global__ void build_hp(const float* __restrict__ intra_x,
                         const float* __restrict__ intra_h, float* __restrict__ hp) {
    int idx = blockIdx.x * blockDim.x + threadIdx.x;
    if (idx >= BS * 257) return;
    int i = idx / 257, c = idx % 257;
    hp[i * 288 + c] = (c < 256) ? intra_h[i * 256 + c] : intra_x[i * 128 + 127];
}

__global__ void build_feat(const float* __restrict__ intra_x, const float* __restrict__ wr,
                           const float* __restrict__ vv, const float* __restrict__ vh,
                           const float* __restrict__ intra_h, float* __restrict__ feat) {
    int idx = blockIdx.x * blockDim.x + threadIdx.x;
    if (idx >= BS * 640) return;
    float e0 = expf(wr[0]), e1 = expf(wr[1]);
    float w0 = e0 / (e0 + e1), w1 = 1.f - w0;
    int i = idx / 640, c = idx % 640;
    float v;
    if (c < 256) v = w0 * vv[i * 256 + c] + w1 * vh[i * 256 + c];
    else if (c < 512) v = intra_h[i * 256 + (c - 256)];
    else if (c < 639) v = intra_x[i * 128 + (c - 512)];
    else v = 0.f;
    feat[idx] = v;
}

// ---------------- attention cores ----------------
__global__ void inter_attn(const float* __restrict__ qi, const float* __restrict__ ki,
                           const float* __restrict__ vi, float* __restrict__ oi) {
    int i = blockIdx.x;
    int tid = threadIdx.x;
    __shared__ float p[12];
    if (tid < 12) {
        int h = tid / 6, rr = tid % 6;
        const float* qp = qi + i * 256 + h * 128;
        const float* kp = ki + (i * 6 + rr) * 256 + h * 128;
        float acc = 0.f;
        for (int d = 0; d < 128; d++) acc += qp[d] * kp[d];
        p[tid] = acc * 0.08838834764831843f;
    }
    __syncthreads();
    if (tid < 2) {
        float mx = -1e30f;
        for (int r = 0; r < 6; r++) mx = fmaxf(mx, p[tid * 6 + r]);
        float sum = 0.f;
        for (int r = 0; r < 6; r++) { float e = expf(p[tid * 6 + r] - mx); p[tid * 6 + r] = e; sum += e; }
        float inv = 1.f / sum;
        for (int r = 0; r < 6; r++) p[tid * 6 + r] *= inv;
    }
    __syncthreads();
    for (int dd = tid; dd < 256; dd += 128) {
        int h = dd >> 7;
        float acc = 0.f;
        for (int r = 0; r < 6; r++) acc += p[h * 6 + r] * vi[(i * 6 + r) * 256 + dd];
        oi[i * 256 + dd] = acc;
    }
}

__global__ void intra_attn(const float* __restrict__ qh, const float* __restrict__ kh,
                           const float* __restrict__ vhp, float* __restrict__ oh) {
    int tq = blockIdx.x, head = blockIdx.y, b = blockIdx.z;
    int tid = threadIdx.x;
    __shared__ float p[64];
    __shared__ float invsum;
    const float* qp = qh + (b * 64 + tq) * 256 + head * 128;
    if (tid < 64) {
        float s = 0.f;
        if (tid <= tq) {
            const float* kp = kh + (b * 64 + tid) * 256 + head * 128;
            float acc = 0.f;
            for (int d = 0; d < 128; d++) acc += qp[d] * kp[d];
            s = acc * 0.08838834764831843f;
        }
        p[tid] = s;
    }
    __syncthreads();
    if (tid == 0) {
        float mx = -1e30f;
        for (int k = 0; k <= tq; k++) mx = fmaxf(mx, p[k]);
        float sum = 0.f;
        for (int k = 0; k <= tq; k++) { float e = expf(p[k] - mx); p[k] = e; sum += e; }
        invsum = 1.f / sum;
    }
    __syncthreads();
    float inv = invsum;
    {
        int d = tid;
        float acc = 0.f;
        for (int k = 0; k <= tq; k++) acc += p[k] * vhp[(b * 64 + k) * 256 + head * 128 + d];
        oh[(b * 64 + tq) * 256 + head * 128 + d] = acc * inv;
    }
}

// ---------------- launch ----------------
extern "C" void kernel_launch(void* const* d_in, const int* in_sizes, int n_in,
                              void* d_out, int out_size) {
    const float* intra_x   = (const float*)d_in[0];
    const float* inter_his = (const float*)d_in[1];
    const float* inter_r   = (const float*)d_in[2];
    const int*   inter_len = (const int*)d_in[4];
    const float* w_ih = (const float*)d_in[5];
    const float* w_hh = (const float*)d_in[6];
    const float* b_ih = (const float*)d_in[7];
    const float* b_hh = (const float*)d_in[8];
    const float* iq_w = (const float*)d_in[9];
    const float* iq_b = (const float*)d_in[10];
    const float* ik_w = (const float*)d_in[11];
    const float* ik_b = (const float*)d_in[12];
    const float* iv_w = (const float*)d_in[13];
    const float* iv_b = (const float*)d_in[14];
    const float* io_w = (const float*)d_in[15];
    const float* io_b = (const float*)d_in[16];
    const float* aq_w = (const float*)d_in[17];
    const float* aq_b = (const float*)d_in[18];
    const float* ak_w = (const float*)d_in[19];
    const float* ak_b = (const float*)d_in[20];
    const float* av_w = (const float*)d_in[21];
    const float* av_b = (const float*)d_in[22];
    const float* ao_w = (const float*)d_in[23];
    const float* ao_b = (const float*)d_in[24];
    const float* wr   = (const float*)d_in[25];
    const float* ln_w = (const float*)d_in[26];
    const float* ln_b = (const float*)d_in[27];
    float* out = (float*)d_out;

    float *p_xw_inter, *p_xw_intra, *p_gh, *p_hA, *p_hB, *p_his, *p_ih, *p_Mrv, *p_mpv, *p_hp;
    float *p_qi, *p_ki, *p_vi, *p_oi, *p_vv, *p_qh, *p_kh, *p_vhp, *p_oh, *p_vh, *p_feat;
    float *p_Wq, *p_Wk, *p_Waq, *p_Wak, *p_Wav, *p_Wln;
    cudaGetSymbolAddress((void**)&p_xw_inter, g_xw_inter);
    cudaGetSymbolAddress((void**)&p_xw_intra, g_xw_intra);
    cudaGetSymbolAddress((void**)&p_gh, g_gh);
    cudaGetSymbolAddress((void**)&p_hA, g_hA);
    cudaGetSymbolAddress((void**)&p_hB, g_hB);
    cudaGetSymbolAddress((void**)&p_his, g_his_last);
    cudaGetSymbolAddress((void**)&p_ih, g_intra_h);
    cudaGetSymbolAddress((void**)&p_Mrv, g_Mrv);
    cudaGetSymbolAddress((void**)&p_mpv, g_mpv);
    cudaGetSymbolAddress((void**)&p_hp, g_hp);
    cudaGetSymbolAddress((void**)&p_qi, g_qi);
    cudaGetSymbolAddress((void**)&p_ki, g_ki);
    cudaGetSymbolAddress((void**)&p_vi, g_vi);
    cudaGetSymbolAddress((void**)&p_oi, g_oi);
    cudaGetSymbolAddress((void**)&p_vv, g_vv);
    cudaGetSymbolAddress((void**)&p_qh, g_qh);
    cudaGetSymbolAddress((void**)&p_kh, g_kh);
    cudaGetSymbolAddress((void**)&p_vhp, g_vhp);
    cudaGetSymbolAddress((void**)&p_oh, g_oh);
    cudaGetSymbolAddress((void**)&p_vh, g_vh);
    cudaGetSymbolAddress((void**)&p_feat, g_feat);
    cudaGetSymbolAddress((void**)&p_Wq, g_Wq);
    cudaGetSymbolAddress((void**)&p_Wk, g_Wk);
    cudaGetSymbolAddress((void**)&p_Waq, g_Waq);
    cudaGetSymbolAddress((void**)&p_Wak, g_Wak);
    cudaGetSymbolAddress((void**)&p_Wav, g_Wav);
    cudaGetSymbolAddress((void**)&p_Wln, g_Wln);

    // weight padding
    pad_w<<<(256 * 384 + 255) / 256, 256>>>(iq_w, p_Wq, 256, 383, 384);
    pad_w<<<(256 * 384 + 255) / 256, 256>>>(ik_w, p_Wk, 256, 383, 384);
    pad_w<<<(256 * 128 + 255) / 256, 256>>>(aq_w, p_Waq, 256, 127, 128);
    pad_w<<<(256 * 128 + 255) / 256, 256>>>(ak_w, p_Wak, 256, 127, 128);
    pad_w<<<(256 * 288 + 255) / 256, 256>>>(av_w, p_Wav, 256, 257, 288);
    pad_w<<<(256 * 640 + 255) / 256, 256>>>(ln_w, p_Wln, 256, 639, 640);

    // hoisted input projections (tensor cores)
    gemm_tc<<<dim3(NROWS_XW / 128, 12), 256>>>(NROWS_XW, 768, 128, inter_his, 128,
                                               w_ih, 128, nullptr, p_xw_inter, 768);
    gemm_tc<<<dim3(8, 12), 256>>>(BS, 768, 128, intra_x, 128, w_ih, 128, nullptr, p_xw_intra, 768);

    // inter GRU: 24 steps; gh = h @ w_hh^T on tensor cores, then gating
    for (int t = 0; t < Ll; t++) {
        float* h_out  = (t & 1) ? p_hB : p_hA;
        float* h_prev = (t & 1) ? p_hA : p_hB;
        if (t > 0)
            gemm_tc<<<dim3(48, 12), 256>>>(NSEQ, 768, 256, h_prev, 256, w_hh, 256,
                                           nullptr, p_gh, 768);
        gru_gate<<<(NSEQ * 64 + 255) / 256, 256>>>(t, t > 0 ? 1 : 0, p_xw_inter, p_gh,
                                                   h_prev, h_out, b_ih, b_hh,
                                                   inter_len, p_his);
    }

    // intra GRU: fused, one launch
    intra_gru<<<Bb, 768>>>(p_xw_intra, w_hh, b_ih, b_hh, p_ih);

    // builders
    build_mrv<<<(NSEQ * 384 + 255) / 256, 256>>>(inter_r, p_his, p_Mrv);
    build_mpv<<<(BS * 384 + 255) / 256, 256>>>(intra_x, p_ih, p_mpv);
    build_hp<<<(BS * 257 + 255) / 256, 256>>>(intra_x, p_ih, p_hp);

    // inter MHA
    gemm_tc<<<dim3(8, 4), 256>>>(BS, 256, 384, p_mpv, 384, p_Wq, 384, iq_b, p_qi, 256);
    gemm_tc<<<dim3(48, 4), 256>>>(NSEQ, 256, 384, p_Mrv, 384, p_Wk, 384, ik_b, p_ki, 256);
    gemm_tc<<<dim3(48, 4), 256>>>(NSEQ, 256, 384, p_Mrv, 384, iv_w, 384, iv_b, p_vi, 256);
    inter_attn<<<BS, 128>>>(p_qi, p_ki, p_vi, p_oi);
    gemm_tc<<<dim3(8, 4), 256>>>(BS, 256, 256, p_oi, 256, io_w, 256, io_b, p_vv, 256);

    // intra MHA
    gemm_tc<<<dim3(8, 4), 256>>>(BS, 256, 128, intra_x, 128, p_Waq, 128, aq_b, p_qh, 256);
    gemm_tc<<<dim3(8, 4), 256>>>(BS, 256, 128, intra_x, 128, p_Wak, 128, ak_b, p_kh, 256);
    gemm_tc<<<dim3(8, 4), 256>>>(BS, 256, 288, p_hp, 288, p_Wav, 288, av_b, p_vhp, 256);
    intra_attn<<<dim3(64, 2, 16), 128>>>(p_qh, p_kh, p_vhp, p_oh);
    gemm_tc<<<dim3(8, 4), 256>>>(BS, 256, 256, p_oh, 256, ao_w, 256, ao_b, p_vh, 256);

    // combine + final projection
    build_feat<<<(BS * 640 + 255) / 256, 256>>>(intra_x, wr, p_vv, p_vh, p_ih, p_feat);
    gemm_tc<<<dim3(8, 4), 256>>>(BS, 256, 640, p_feat, 640, p_Wln, 640, ln_b, out, 256);
}